// round 3
// baseline (speedup 1.0000x reference)
#include <cuda_runtime.h>
#include <cuda_bf16.h>
#include <stdint.h>

#define IN_F  4096
#define OUT_F 4096
#define BATCH 4096

// ---------------- scratch (static device globals; no allocation) ----------------
__device__ __align__(16) signed char g_wq8[(size_t)OUT_F * IN_F];   // 16 MB
__device__ __align__(16) signed char g_xq1[(size_t)BATCH * IN_F];   // 16 MB
__device__ __align__(16) signed char g_xq2[(size_t)BATCH * IN_F];   // 16 MB
__device__ float g_rowsum[BATCH];
__device__ int   g_wmm[2];    // weight q min, max
__device__ int   g_bmm[2];    // bias   q min, max
__device__ int   g_xamax_i;   // |x| max as ordered int bits
__device__ float g_scal[6];   // s_w, off_w, s_b, off_b, s_x, inv_s_x

// ---------------- PTX helpers (legal at compute_103) ----------------
__device__ __forceinline__ uint32_t smem_u32(const void* p) {
    uint32_t a;
    asm("{ .reg .u64 t; cvta.to.shared.u64 t, %1; cvt.u32.u64 %0, t; }" : "=r"(a) : "l"(p));
    return a;
}

#define CP_ASYNC16(dst, src) \
    asm volatile("cp.async.cg.shared.global [%0], [%1], 16;" :: "r"(dst), "l"(src))
#define CP_COMMIT() asm volatile("cp.async.commit_group;" ::: "memory")
#define CP_WAIT(n)  asm volatile("cp.async.wait_group %0;" :: "n"(n) : "memory")

__device__ __forceinline__ void ldsm_x4(uint32_t& d0, uint32_t& d1, uint32_t& d2, uint32_t& d3,
                                        uint32_t addr) {
    asm volatile("ldmatrix.sync.aligned.m8n8.x4.shared.b16 {%0,%1,%2,%3}, [%4];"
                 : "=r"(d0), "=r"(d1), "=r"(d2), "=r"(d3) : "r"(addr));
}

// int8 MMA: D(s32) += A(s8,16x32) * B(s8,32x8)
__device__ __forceinline__ void mma_s8(int& c0, int& c1, int& c2, int& c3,
                                       uint32_t a0, uint32_t a1, uint32_t a2, uint32_t a3,
                                       uint32_t b0, uint32_t b1) {
    asm volatile(
        "mma.sync.aligned.m16n8k32.row.col.s32.s8.s8.s32 "
        "{%0,%1,%2,%3}, {%4,%5,%6,%7}, {%8,%9}, {%0,%1,%2,%3};"
        : "+r"(c0), "+r"(c1), "+r"(c2), "+r"(c3)
        : "r"(a0), "r"(a1), "r"(a2), "r"(a3), "r"(b0), "r"(b1));
}

// ---------------- prepass kernels ----------------
__global__ void k_init() {
    g_wmm[0] = 0x7fffffff; g_wmm[1] = (int)0x80000000;
    g_bmm[0] = 0x7fffffff; g_bmm[1] = (int)0x80000000;
    g_xamax_i = 0;
}

// int32 weights -> int8 buffer + global min/max
__global__ void k_wconv(const int* __restrict__ wq) {
    int i = blockIdx.x * blockDim.x + threadIdx.x;     // one int4 per thread
    int4 v = ((const int4*)wq)[i];
    char4 c;
    c.x = (signed char)v.x; c.y = (signed char)v.y;
    c.z = (signed char)v.z; c.w = (signed char)v.w;
    ((char4*)g_wq8)[i] = c;
    int mn = min(min(v.x, v.y), min(v.z, v.w));
    int mx = max(max(v.x, v.y), max(v.z, v.w));
    #pragma unroll
    for (int o = 16; o > 0; o >>= 1) {
        mn = min(mn, __shfl_xor_sync(0xffffffffu, mn, o));
        mx = max(mx, __shfl_xor_sync(0xffffffffu, mx, o));
    }
    if ((threadIdx.x & 31) == 0) {
        atomicMin(&g_wmm[0], mn);
        atomicMax(&g_wmm[1], mx);
    }
}

__global__ void k_bias_mm(const int* __restrict__ bq) {
    int t = threadIdx.x;
    int mn = 0x7fffffff, mx = (int)0x80000000;
    for (int i = t; i < OUT_F; i += 256) {
        int v = bq[i];
        mn = min(mn, v); mx = max(mx, v);
    }
    #pragma unroll
    for (int o = 16; o > 0; o >>= 1) {
        mn = min(mn, __shfl_xor_sync(0xffffffffu, mn, o));
        mx = max(mx, __shfl_xor_sync(0xffffffffu, mx, o));
    }
    if ((t & 31) == 0) {
        atomicMin(&g_bmm[0], mn);
        atomicMax(&g_bmm[1], mx);
    }
}

// global amax(|x|) (nonneg float bits compare as ints)
__global__ void k_xamax(const float* __restrict__ x) {
    size_t i0 = (size_t)(blockIdx.x * blockDim.x + threadIdx.x);
    size_t stride = (size_t)gridDim.x * blockDim.x;
    const float4* x4 = (const float4*)x;
    size_t n4 = (size_t)BATCH * IN_F / 4;
    float am = 0.f;
    for (size_t i = i0; i < n4; i += stride) {
        float4 v = x4[i];
        am = fmaxf(am, fmaxf(fmaxf(fabsf(v.x), fabsf(v.y)), fmaxf(fabsf(v.z), fabsf(v.w))));
    }
    #pragma unroll
    for (int o = 16; o > 0; o >>= 1)
        am = fmaxf(am, __int_as_float(__shfl_xor_sync(0xffffffffu, __float_as_int(am), o)));
    if ((threadIdx.x & 31) == 0) atomicMax(&g_xamax_i, __float_as_int(am));
}

__global__ void k_scal(const float* wmin, const float* wmax, const float* bmin, const float* bmax) {
    float s_w = (*wmax - *wmin) / (float)(g_wmm[1] - g_wmm[0]);
    g_scal[0] = s_w;
    g_scal[1] = *wmin - s_w * (float)g_wmm[0];
    float s_b = (*bmax - *bmin) / (float)(g_bmm[1] - g_bmm[0]);
    g_scal[2] = s_b;
    g_scal[3] = *bmin - s_b * (float)g_bmm[0];
    float amax = __int_as_float(g_xamax_i);
    float s_x = amax > 0.f ? amax / 16255.0f : 1.0f;
    g_scal[4] = s_x;
    g_scal[5] = 1.0f / s_x;
}

// x fp32 -> 15-bit fixed point (q1,q2 int8) + per-row sum
__global__ void k_xquant(const float* __restrict__ x) {
    __shared__ float red[8];
    int row = blockIdx.x;
    int t = threadIdx.x;
    float inv = g_scal[5];
    const float4* xr = (const float4*)(x + (size_t)row * IN_F);
    uint32_t o1[4], o2[4];
    float s = 0.f;
    #pragma unroll
    for (int j = 0; j < 4; j++) {
        float4 v = xr[t * 4 + j];
        s += v.x + v.y + v.z + v.w;
        int Q0 = __float2int_rn(v.x * inv);
        int Q1 = __float2int_rn(v.y * inv);
        int Q2 = __float2int_rn(v.z * inv);
        int Q3 = __float2int_rn(v.w * inv);
        int a0 = Q0 >> 7, a1 = Q1 >> 7, a2 = Q2 >> 7, a3 = Q3 >> 7;
        int b0 = Q0 - (a0 << 7), b1 = Q1 - (a1 << 7), b2 = Q2 - (a2 << 7), b3 = Q3 - (a3 << 7);
        o1[j] = (a0 & 0xff) | ((a1 & 0xff) << 8) | ((a2 & 0xff) << 16) | ((a3 & 0xff) << 24);
        o2[j] = (b0 & 0xff) | ((b1 & 0xff) << 8) | ((b2 & 0xff) << 16) | ((b3 & 0xff) << 24);
    }
    size_t base = ((size_t)row * IN_F) / 16 + t;
    ((uint4*)g_xq1)[base] = make_uint4(o1[0], o1[1], o1[2], o1[3]);
    ((uint4*)g_xq2)[base] = make_uint4(o2[0], o2[1], o2[2], o2[3]);
    #pragma unroll
    for (int o = 16; o > 0; o >>= 1) s += __shfl_xor_sync(0xffffffffu, s, o);
    if ((t & 31) == 0) red[t >> 5] = s;
    __syncthreads();
    if (t == 0) {
        float tot = 0.f;
        #pragma unroll
        for (int i = 0; i < 8; i++) tot += red[i];
        g_rowsum[row] = tot;
    }
}

// ---------------- GEMM ----------------
// CTA tile: 64 (M) x 256 (N), BK=128 int8 (128B rows), 8 warps (2x4 of 32x64),
// 4-stage cp.async pipeline, SW128 swizzle, mma.sync m16n8k32 s8.
#define BM      64
#define BN      256
#define BK      128
#define NSTAGE  4
#define NSTEPS  (IN_F / BK)          // 32
#define A_BYTES (BM * 128)           // 8192 per operand (q1 or q2)
#define B_BYTES (BN * 128)           // 32768
#define STG_B   (2 * A_BYTES + B_BYTES)   // 49152
#define OFF_A1  0
#define OFF_A2  A_BYTES
#define OFF_B   (2 * A_BYTES)
#define SM_TOTAL (NSTAGE * STG_B)    // 196608

__device__ __forceinline__ void issue_stage(char* smem, int stage, int tid,
                                            const signed char* a1,
                                            const signed char* a2,
                                            const signed char* bsrc, int k0) {
    uint32_t ubase = smem_u32(smem + stage * STG_B);
    // A: 64 rows x 8 chunks of 16B; 4 threads per row, 2 chunks each per operand
    {
        int r = tid >> 2;
        int c0 = (tid & 3) * 2;
        const char* s1 = (const char*)(a1 + (size_t)r * IN_F + k0);
        const char* s2 = (const char*)(a2 + (size_t)r * IN_F + k0);
        uint32_t rb = ubase + r * 128;
        int rx = r & 7;
        #pragma unroll
        for (int c = 0; c < 2; c++) {
            uint32_t sw = ((c0 + c) ^ rx) * 16;
            CP_ASYNC16(rb + OFF_A1 + sw, s1 + (c0 + c) * 16);
            CP_ASYNC16(rb + OFF_A2 + sw, s2 + (c0 + c) * 16);
        }
    }
    // B: 256 rows x 8 chunks; 1 thread per row, 8 chunks each
    {
        int r = tid;
        const char* src = (const char*)(bsrc + (size_t)r * IN_F + k0);
        uint32_t rb = ubase + OFF_B + r * 128;
        int rx = r & 7;
        #pragma unroll
        for (int c = 0; c < 8; c++)
            CP_ASYNC16(rb + (c ^ rx) * 16, src + c * 16);
    }
}

__global__ void __launch_bounds__(256, 1) k_gemm(const int* __restrict__ bias_q,
                                                 float* __restrict__ out) {
    extern __shared__ char smem[];
    int tid = threadIdx.x;
    int wid = tid >> 5, lid = tid & 31;
    int n0 = blockIdx.x * BN;
    int m0 = blockIdx.y * BM;
    int wm = (wid & 1) * 32;          // warp m offset (2 slots)
    int wn = (wid >> 1) * 64;         // warp n offset (4 slots)

    const signed char* a1src = g_xq1 + (size_t)m0 * IN_F;
    const signed char* a2src = g_xq2 + (size_t)m0 * IN_F;
    const signed char* bsrc  = g_wq8 + (size_t)n0 * IN_F;

    int acc1[2][8][4], acc2[2][8][4];
    #pragma unroll
    for (int i = 0; i < 2; i++)
        #pragma unroll
        for (int j = 0; j < 8; j++)
            #pragma unroll
            for (int q = 0; q < 4; q++) { acc1[i][j][q] = 0; acc2[i][j][q] = 0; }

    int lrow = lid & 15;
    int lkc  = (lid >> 4) & 1;        // second 16B chunk for lanes 16-31
    int lx   = lrow & 7;              // swizzle xor
    uint32_t sbase = smem_u32(smem);

    uint32_t aRowOff[2], bRowOff[4];
    #pragma unroll
    for (int f = 0; f < 2; f++) aRowOff[f] = (wm + f * 16 + lrow) * 128;
    #pragma unroll
    for (int f = 0; f < 4; f++) bRowOff[f] = OFF_B + (wn + f * 16 + lrow) * 128;

    issue_stage(smem, 0, tid, a1src, a2src, bsrc, 0);
    CP_COMMIT();
    issue_stage(smem, 1, tid, a1src, a2src, bsrc, BK);
    CP_COMMIT();
    issue_stage(smem, 2, tid, a1src, a2src, bsrc, 2 * BK);
    CP_COMMIT();

    for (int s = 0; s < NSTEPS; s++) {
        CP_WAIT(2);
        __syncthreads();
        if (s + 3 < NSTEPS)
            issue_stage(smem, (s + 3) % NSTAGE, tid, a1src, a2src, bsrc, (s + 3) * BK);
        CP_COMMIT();   // unconditional: keeps group arithmetic valid at the tail
        uint32_t stg = sbase + (s % NSTAGE) * STG_B;
        #pragma unroll
        for (int c = 0; c < 4; c++) {            // four k32 chunks per stage
            int kc = c * 2 + lkc;                // 16B chunk index within 128B row
            uint32_t b[8][2];
            #pragma unroll
            for (int f = 0; f < 4; f++) {
                uint32_t q0, q1r, q2r, q3;
                ldsm_x4(q0, q1r, q2r, q3, stg + bRowOff[f] + ((kc ^ lx) * 16));
                b[2 * f][0] = q0; b[2 * f + 1][0] = q1r;
                b[2 * f][1] = q2r; b[2 * f + 1][1] = q3;
            }
            uint32_t a[2][4];
            // q1 pass
            #pragma unroll
            for (int f = 0; f < 2; f++)
                ldsm_x4(a[f][0], a[f][1], a[f][2], a[f][3],
                        stg + OFF_A1 + aRowOff[f] + ((kc ^ lx) * 16));
            #pragma unroll
            for (int mf = 0; mf < 2; mf++)
                #pragma unroll
                for (int nf = 0; nf < 8; nf++)
                    mma_s8(acc1[mf][nf][0], acc1[mf][nf][1], acc1[mf][nf][2], acc1[mf][nf][3],
                           a[mf][0], a[mf][1], a[mf][2], a[mf][3], b[nf][0], b[nf][1]);
            // q2 pass (B frags reused)
            #pragma unroll
            for (int f = 0; f < 2; f++)
                ldsm_x4(a[f][0], a[f][1], a[f][2], a[f][3],
                        stg + OFF_A2 + aRowOff[f] + ((kc ^ lx) * 16));
            #pragma unroll
            for (int mf = 0; mf < 2; mf++)
                #pragma unroll
                for (int nf = 0; nf < 8; nf++)
                    mma_s8(acc2[mf][nf][0], acc2[mf][nf][1], acc2[mf][nf][2], acc2[mf][nf][3],
                           a[mf][0], a[mf][1], a[mf][2], a[mf][3], b[nf][0], b[nf][1]);
        }
        __syncthreads();
    }

    // ---------------- epilogue: y = s_w*s_x*(128*D1 + D2) + off_w*rowsum + bias ----------------
    float sws = g_scal[0] * g_scal[4];
    float off_w = g_scal[1];
    float s_b = g_scal[2], off_b = g_scal[3];
    float rs0[2], rs1[2];
    #pragma unroll
    for (int mf = 0; mf < 2; mf++) {
        int r = m0 + wm + mf * 16 + (lid >> 2);
        rs0[mf] = off_w * g_rowsum[r];
        rs1[mf] = off_w * g_rowsum[r + 8];
    }
    float bv[8][2];
    #pragma unroll
    for (int nf = 0; nf < 8; nf++) {
        int c = n0 + wn + nf * 8 + (lid & 3) * 2;
        bv[nf][0] = fmaf(s_b, (float)bias_q[c], off_b);
        bv[nf][1] = fmaf(s_b, (float)bias_q[c + 1], off_b);
    }
    #pragma unroll
    for (int mf = 0; mf < 2; mf++) {
        int r0 = m0 + wm + mf * 16 + (lid >> 2);
        #pragma unroll
        for (int nf = 0; nf < 8; nf++) {
            int c = n0 + wn + nf * 8 + (lid & 3) * 2;
            float d0 = fmaf(128.f, (float)acc1[mf][nf][0], (float)acc2[mf][nf][0]);
            float d1 = fmaf(128.f, (float)acc1[mf][nf][1], (float)acc2[mf][nf][1]);
            float d2 = fmaf(128.f, (float)acc1[mf][nf][2], (float)acc2[mf][nf][2]);
            float d3 = fmaf(128.f, (float)acc1[mf][nf][3], (float)acc2[mf][nf][3]);
            float2 v0, v1;
            v0.x = fmaf(sws, d0, rs0[mf] + bv[nf][0]);
            v0.y = fmaf(sws, d1, rs0[mf] + bv[nf][1]);
            v1.x = fmaf(sws, d2, rs1[mf] + bv[nf][0]);
            v1.y = fmaf(sws, d3, rs1[mf] + bv[nf][1]);
            *(float2*)(out + (size_t)r0 * OUT_F + c)       = v0;
            *(float2*)(out + (size_t)(r0 + 8) * OUT_F + c) = v1;
        }
    }
}

// ---------------- launch ----------------
extern "C" void kernel_launch(void* const* d_in, const int* in_sizes, int n_in,
                              void* d_out, int out_size) {
    const float* x    = (const float*)d_in[0];
    const int*   wq   = (const int*)d_in[1];
    const int*   bq   = (const int*)d_in[2];
    const float* wmin = (const float*)d_in[3];
    const float* wmax = (const float*)d_in[4];
    const float* bmin = (const float*)d_in[5];
    const float* bmax = (const float*)d_in[6];
    float* out = (float*)d_out;

    k_init<<<1, 1>>>();
    k_wconv<<<((size_t)OUT_F * IN_F / 4) / 256, 256>>>(wq);
    k_bias_mm<<<1, 256>>>(bq);
    k_xamax<<<512, 256>>>(x);
    k_scal<<<1, 1>>>(wmin, wmax, bmin, bmax);
    k_xquant<<<BATCH, 256>>>(x);

    cudaFuncSetAttribute(k_gemm, cudaFuncAttributeMaxDynamicSharedMemorySize, SM_TOTAL);
    k_gemm<<<dim3(OUT_F / BN, BATCH / BM), 256, SM_TOTAL>>>(bq, out);
}

// round 4
// speedup vs baseline: 2.5902x; 2.5902x over previous
#include <cuda_runtime.h>
#include <cuda_fp16.h>
#include <stdint.h>

#define IN_F  4096
#define OUT_F 4096
#define BATCH 4096

// ---------------- scratch (static device globals; no allocation) ----------------
__device__ __align__(16) __half g_wh[(size_t)OUT_F * IN_F];   // 32 MB
__device__ __align__(16) __half g_xh[(size_t)BATCH * IN_F];   // 32 MB
__device__ float g_rowsum[BATCH];
__device__ int   g_wmm[2];    // weight q min, max
__device__ int   g_bmm[2];    // bias   q min, max
__device__ float g_scal[4];   // s_w, off_w, s_b, off_b

// ---------------- PTX helpers (legal at compute_103) ----------------
__device__ __forceinline__ uint32_t smem_u32(const void* p) {
    uint32_t a;
    asm("{ .reg .u64 t; cvta.to.shared.u64 t, %1; cvt.u32.u64 %0, t; }" : "=r"(a) : "l"(p));
    return a;
}

#define CP_ASYNC16(dst, src) \
    asm volatile("cp.async.cg.shared.global [%0], [%1], 16;" :: "r"(dst), "l"(src))
#define CP_COMMIT() asm volatile("cp.async.commit_group;" ::: "memory")
#define CP_WAIT(n)  asm volatile("cp.async.wait_group %0;" :: "n"(n) : "memory")

__device__ __forceinline__ void ldsm_x4(uint32_t& d0, uint32_t& d1, uint32_t& d2, uint32_t& d3,
                                        uint32_t addr) {
    asm volatile("ldmatrix.sync.aligned.m8n8.x4.shared.b16 {%0,%1,%2,%3}, [%4];"
                 : "=r"(d0), "=r"(d1), "=r"(d2), "=r"(d3) : "r"(addr));
}

__device__ __forceinline__ void mma16816(float& c0, float& c1, float& c2, float& c3,
                                         uint32_t a0, uint32_t a1, uint32_t a2, uint32_t a3,
                                         uint32_t b0, uint32_t b1) {
    asm volatile(
        "mma.sync.aligned.m16n8k16.row.col.f32.f16.f16.f32 "
        "{%0,%1,%2,%3}, {%4,%5,%6,%7}, {%8,%9}, {%0,%1,%2,%3};"
        : "+f"(c0), "+f"(c1), "+f"(c2), "+f"(c3)
        : "r"(a0), "r"(a1), "r"(a2), "r"(a3), "r"(b0), "r"(b1));
}

// ---------------- prepass kernels ----------------
__global__ void k_init() {
    g_wmm[0] = 0x7fffffff; g_wmm[1] = (int)0x80000000;
    g_bmm[0] = 0x7fffffff; g_bmm[1] = (int)0x80000000;
}

// int32 weights -> fp16 (exact: |q| <= 128) + global min/max
__global__ void k_wconv(const int* __restrict__ wq) {
    int i = blockIdx.x * blockDim.x + threadIdx.x;     // one int4 per thread
    int4 v = ((const int4*)wq)[i];
    __half2 p0 = __floats2half2_rn((float)v.x, (float)v.y);
    __half2 p1 = __floats2half2_rn((float)v.z, (float)v.w);
    uint2 o;
    o.x = *(uint32_t*)&p0;
    o.y = *(uint32_t*)&p1;
    ((uint2*)g_wh)[i] = o;
    int mn = min(min(v.x, v.y), min(v.z, v.w));
    int mx = max(max(v.x, v.y), max(v.z, v.w));
    #pragma unroll
    for (int o2 = 16; o2 > 0; o2 >>= 1) {
        mn = min(mn, __shfl_xor_sync(0xffffffffu, mn, o2));
        mx = max(mx, __shfl_xor_sync(0xffffffffu, mx, o2));
    }
    if ((threadIdx.x & 31) == 0) {
        atomicMin(&g_wmm[0], mn);
        atomicMax(&g_wmm[1], mx);
    }
}

__global__ void k_bias_mm(const int* __restrict__ bq) {
    int t = threadIdx.x;
    int mn = 0x7fffffff, mx = (int)0x80000000;
    for (int i = t; i < OUT_F; i += 256) {
        int v = bq[i];
        mn = min(mn, v); mx = max(mx, v);
    }
    #pragma unroll
    for (int o = 16; o > 0; o >>= 1) {
        mn = min(mn, __shfl_xor_sync(0xffffffffu, mn, o));
        mx = max(mx, __shfl_xor_sync(0xffffffffu, mx, o));
    }
    if ((t & 31) == 0) {
        atomicMin(&g_bmm[0], mn);
        atomicMax(&g_bmm[1], mx);
    }
}

// x fp32 -> fp16 + per-row sum
__global__ void k_xcvt(const float* __restrict__ x) {
    __shared__ float red[8];
    int row = blockIdx.x;
    int t = threadIdx.x;
    const float4* xr = (const float4*)(x + (size_t)row * IN_F);
    uint32_t o[4];
    float s = 0.f;
    #pragma unroll
    for (int j = 0; j < 4; j++) {
        float4 v = xr[t * 4 + j];
        s += v.x + v.y + v.z + v.w;
        __half2 p0 = __floats2half2_rn(v.x, v.y);
        __half2 p1 = __floats2half2_rn(v.z, v.w);
        o[2 * (j & 1)]     = *(uint32_t*)&p0;
        o[2 * (j & 1) + 1] = *(uint32_t*)&p1;
        if (j & 1) {
            size_t base = ((size_t)row * IN_F) / 8 + t * 2 + (j >> 1);
            ((uint4*)g_xh)[base] = make_uint4(o[0], o[1], o[2], o[3]);
        }
    }
    #pragma unroll
    for (int of = 16; of > 0; of >>= 1) s += __shfl_xor_sync(0xffffffffu, s, of);
    if ((t & 31) == 0) red[t >> 5] = s;
    __syncthreads();
    if (t == 0) {
        float tot = 0.f;
        #pragma unroll
        for (int i = 0; i < 8; i++) tot += red[i];
        g_rowsum[row] = tot;
    }
}

__global__ void k_scal(const float* wmin, const float* wmax, const float* bmin, const float* bmax) {
    float s_w = (*wmax - *wmin) / (float)(g_wmm[1] - g_wmm[0]);
    g_scal[0] = s_w;
    g_scal[1] = *wmin - s_w * (float)g_wmm[0];
    float s_b = (*bmax - *bmin) / (float)(g_bmm[1] - g_bmm[0]);
    g_scal[2] = s_b;
    g_scal[3] = *bmin - s_b * (float)g_bmm[0];
}

// ---------------- GEMM ----------------
// CTA tile: 128 (M) x 256 (N), BK=64 fp16 (128B rows), 8 warps (2x4 of 64x64),
// 4-stage cp.async pipeline, SW128 swizzle, mma.sync m16n8k16 fp16.
#define BM      128
#define BN      256
#define BK      64
#define NSTAGE  4
#define NSTEPS  (IN_F / BK)          // 64
#define A_BYTES (BM * 128)           // 16384
#define B_BYTES (BN * 128)           // 32768
#define STG_B   (A_BYTES + B_BYTES)  // 49152
#define OFF_B   A_BYTES
#define SM_TOTAL (NSTAGE * STG_B)    // 196608

__device__ __forceinline__ void issue_stage(char* smem, int stage, int tid,
                                            const __half* asrc,
                                            const __half* bsrc, int k0) {
    uint32_t ubase = smem_u32(smem + stage * STG_B);
    // A: 128 rows x 8 chunks of 16B; 2 threads per row, 4 chunks each
    {
        int r = tid >> 1;
        int c0 = (tid & 1) * 4;
        const char* src = (const char*)(asrc + (size_t)r * IN_F + k0);
        uint32_t rb = ubase + r * 128;
        int rx = r & 7;
        #pragma unroll
        for (int c = 0; c < 4; c++)
            CP_ASYNC16(rb + (((c0 + c) ^ rx) * 16), src + (c0 + c) * 16);
    }
    // B: 256 rows x 8 chunks; 1 thread per row, 8 chunks each
    {
        int r = tid;
        const char* src = (const char*)(bsrc + (size_t)r * IN_F + k0);
        uint32_t rb = ubase + OFF_B + r * 128;
        int rx = r & 7;
        #pragma unroll
        for (int c = 0; c < 8; c++)
            CP_ASYNC16(rb + ((c ^ rx) * 16), src + c * 16);
    }
}

__global__ void __launch_bounds__(256, 1) k_gemm(const int* __restrict__ bias_q,
                                                 float* __restrict__ out) {
    extern __shared__ char smem[];
    int tid = threadIdx.x;
    int wid = tid >> 5, lid = tid & 31;
    int n0 = blockIdx.x * BN;
    int m0 = blockIdx.y * BM;
    int wm = (wid >> 2) * 64;        // warp m offset
    int wn = (wid & 3) * 64;         // warp n offset

    const __half* asrc = g_xh + (size_t)m0 * IN_F;
    const __half* bsrc = g_wh + (size_t)n0 * IN_F;

    float acc[4][8][4];
    #pragma unroll
    for (int i = 0; i < 4; i++)
        #pragma unroll
        for (int j = 0; j < 8; j++)
            #pragma unroll
            for (int q = 0; q < 4; q++) acc[i][j][q] = 0.f;

    int lrow = lid & 15;
    int lkc  = (lid >> 4) & 1;       // extra 16B k-chunk for lanes 16-31
    int lx   = lrow & 7;             // swizzle xor
    uint32_t sbase = smem_u32(smem);

    uint32_t aRowOff[4], bRowOff[4];
    #pragma unroll
    for (int f = 0; f < 4; f++) {
        aRowOff[f] = (wm + f * 16 + lrow) * 128;
        bRowOff[f] = OFF_B + (wn + f * 16 + lrow) * 128;
    }

    issue_stage(smem, 0, tid, asrc, bsrc, 0);
    CP_COMMIT();
    issue_stage(smem, 1, tid, asrc, bsrc, BK);
    CP_COMMIT();
    issue_stage(smem, 2, tid, asrc, bsrc, 2 * BK);
    CP_COMMIT();

    for (int s = 0; s < NSTEPS; s++) {
        CP_WAIT(2);
        __syncthreads();
        if (s + 3 < NSTEPS)
            issue_stage(smem, (s + 3) % NSTAGE, tid, asrc, bsrc, (s + 3) * BK);
        CP_COMMIT();   // unconditional: keeps group arithmetic valid at the tail
        uint32_t stg = sbase + (s % NSTAGE) * STG_B;
        #pragma unroll
        for (int k16 = 0; k16 < 4; k16++) {
            int kc = k16 * 2 + lkc;          // 16B chunk index within 128B row
            uint32_t b[8][2];
            #pragma unroll
            for (int f = 0; f < 4; f++) {
                uint32_t q0, q1, q2, q3;
                ldsm_x4(q0, q1, q2, q3, stg + bRowOff[f] + ((kc ^ lx) * 16));
                b[2 * f][0] = q0; b[2 * f + 1][0] = q1;
                b[2 * f][1] = q2; b[2 * f + 1][1] = q3;
            }
            uint32_t a[4][4];
            #pragma unroll
            for (int f = 0; f < 4; f++)
                ldsm_x4(a[f][0], a[f][1], a[f][2], a[f][3],
                        stg + aRowOff[f] + ((kc ^ lx) * 16));
            #pragma unroll
            for (int mf = 0; mf < 4; mf++)
                #pragma unroll
                for (int nf = 0; nf < 8; nf++)
                    mma16816(acc[mf][nf][0], acc[mf][nf][1], acc[mf][nf][2], acc[mf][nf][3],
                             a[mf][0], a[mf][1], a[mf][2], a[mf][3],
                             b[nf][0], b[nf][1]);
        }
        __syncthreads();
    }

    // ---------------- epilogue: y = s_w*D + off_w*rowsum + bias_deq ----------------
    float s_w = g_scal[0], off_w = g_scal[1];
    float s_b = g_scal[2], off_b = g_scal[3];
    float rs0[4], rs1[4];
    #pragma unroll
    for (int mf = 0; mf < 4; mf++) {
        int r = m0 + wm + mf * 16 + (lid >> 2);
        rs0[mf] = off_w * g_rowsum[r];
        rs1[mf] = off_w * g_rowsum[r + 8];
    }
    float bv[8][2];
    #pragma unroll
    for (int nf = 0; nf < 8; nf++) {
        int c = n0 + wn + nf * 8 + (lid & 3) * 2;
        bv[nf][0] = fmaf(s_b, (float)bias_q[c], off_b);
        bv[nf][1] = fmaf(s_b, (float)bias_q[c + 1], off_b);
    }
    #pragma unroll
    for (int mf = 0; mf < 4; mf++) {
        int r0 = m0 + wm + mf * 16 + (lid >> 2);
        #pragma unroll
        for (int nf = 0; nf < 8; nf++) {
            int c = n0 + wn + nf * 8 + (lid & 3) * 2;
            float2 v0, v1;
            v0.x = fmaf(s_w, acc[mf][nf][0], rs0[mf] + bv[nf][0]);
            v0.y = fmaf(s_w, acc[mf][nf][1], rs0[mf] + bv[nf][1]);
            v1.x = fmaf(s_w, acc[mf][nf][2], rs1[mf] + bv[nf][0]);
            v1.y = fmaf(s_w, acc[mf][nf][3], rs1[mf] + bv[nf][1]);
            *(float2*)(out + (size_t)r0 * OUT_F + c)       = v0;
            *(float2*)(out + (size_t)(r0 + 8) * OUT_F + c) = v1;
        }
    }
}

// ---------------- launch ----------------
extern "C" void kernel_launch(void* const* d_in, const int* in_sizes, int n_in,
                              void* d_out, int out_size) {
    const float* x    = (const float*)d_in[0];
    const int*   wq   = (const int*)d_in[1];
    const int*   bq   = (const int*)d_in[2];
    const float* wmin = (const float*)d_in[3];
    const float* wmax = (const float*)d_in[4];
    const float* bmin = (const float*)d_in[5];
    const float* bmax = (const float*)d_in[6];
    float* out = (float*)d_out;

    k_init<<<1, 1>>>();
    k_wconv<<<((size_t)OUT_F * IN_F / 4) / 256, 256>>>(wq);
    k_bias_mm<<<1, 256>>>(bq);
    k_xcvt<<<BATCH, 256>>>(x);
    k_scal<<<1, 1>>>(wmin, wmax, bmin, bmax);

    cudaFuncSetAttribute(k_gemm, cudaFuncAttributeMaxDynamicSharedMemorySize, SM_TOTAL);
    k_gemm<<<dim3(OUT_F / BN, BATCH / BM), 256, SM_TOTAL>>>(bq, out);
}

// round 5
// speedup vs baseline: 3.1009x; 1.1972x over previous
#include <cuda_runtime.h>
#include <cuda_fp16.h>
#include <stdint.h>

#define IN_F  4096
#define OUT_F 4096
#define BATCH 4096

// ---------------- scratch (static device globals; no allocation) ----------------
__device__ __align__(16) __half g_wh[(size_t)OUT_F * IN_F];   // 32 MB
__device__ __align__(16) __half g_xh[(size_t)BATCH * IN_F];   // 32 MB
__device__ float g_rowsum[BATCH];
__device__ int   g_wmm[2];    // weight q min, max
__device__ int   g_bmm[2];    // bias   q min, max
__device__ float g_scal[4];   // s_w, off_w, s_b, off_b

// ---------------- PTX helpers (legal at compute_103) ----------------
__device__ __forceinline__ uint32_t smem_u32(const void* p) {
    uint32_t a;
    asm("{ .reg .u64 t; cvta.to.shared.u64 t, %1; cvt.u32.u64 %0, t; }" : "=r"(a) : "l"(p));
    return a;
}

#define CP_ASYNC16(dst, src) \
    asm volatile("cp.async.cg.shared.global [%0], [%1], 16;" :: "r"(dst), "l"(src))
#define CP_COMMIT() asm volatile("cp.async.commit_group;" ::: "memory")
#define CP_WAIT(n)  asm volatile("cp.async.wait_group %0;" :: "n"(n) : "memory")

__device__ __forceinline__ void ldsm_x4(uint32_t& d0, uint32_t& d1, uint32_t& d2, uint32_t& d3,
                                        uint32_t addr) {
    asm volatile("ldmatrix.sync.aligned.m8n8.x4.shared.b16 {%0,%1,%2,%3}, [%4];"
                 : "=r"(d0), "=r"(d1), "=r"(d2), "=r"(d3) : "r"(addr));
}

__device__ __forceinline__ void mma16816(float& c0, float& c1, float& c2, float& c3,
                                         uint32_t a0, uint32_t a1, uint32_t a2, uint32_t a3,
                                         uint32_t b0, uint32_t b1) {
    asm volatile(
        "mma.sync.aligned.m16n8k16.row.col.f32.f16.f16.f32 "
        "{%0,%1,%2,%3}, {%4,%5,%6,%7}, {%8,%9}, {%0,%1,%2,%3};"
        : "+f"(c0), "+f"(c1), "+f"(c2), "+f"(c3)
        : "r"(a0), "r"(a1), "r"(a2), "r"(a3), "r"(b0), "r"(b1));
}

// ---------------- prepass kernels ----------------
__global__ void k_init() {
    g_wmm[0] = 0x7fffffff; g_wmm[1] = (int)0x80000000;
    g_bmm[0] = 0x7fffffff; g_bmm[1] = (int)0x80000000;
}

// int32 weights -> fp16 (exact: |q| <= 128) + global min/max
__global__ void k_wconv(const int* __restrict__ wq) {
    int i = blockIdx.x * blockDim.x + threadIdx.x;     // one int4 per thread
    int4 v = ((const int4*)wq)[i];
    __half2 p0 = __floats2half2_rn((float)v.x, (float)v.y);
    __half2 p1 = __floats2half2_rn((float)v.z, (float)v.w);
    uint2 o;
    o.x = *(uint32_t*)&p0;
    o.y = *(uint32_t*)&p1;
    ((uint2*)g_wh)[i] = o;
    int mn = min(min(v.x, v.y), min(v.z, v.w));
    int mx = max(max(v.x, v.y), max(v.z, v.w));
    #pragma unroll
    for (int o2 = 16; o2 > 0; o2 >>= 1) {
        mn = min(mn, __shfl_xor_sync(0xffffffffu, mn, o2));
        mx = max(mx, __shfl_xor_sync(0xffffffffu, mx, o2));
    }
    if ((threadIdx.x & 31) == 0) {
        atomicMin(&g_wmm[0], mn);
        atomicMax(&g_wmm[1], mx);
    }
}

__global__ void k_bias_mm(const int* __restrict__ bq) {
    int t = threadIdx.x;
    int mn = 0x7fffffff, mx = (int)0x80000000;
    for (int i = t; i < OUT_F; i += 256) {
        int v = bq[i];
        mn = min(mn, v); mx = max(mx, v);
    }
    #pragma unroll
    for (int o = 16; o > 0; o >>= 1) {
        mn = min(mn, __shfl_xor_sync(0xffffffffu, mn, o));
        mx = max(mx, __shfl_xor_sync(0xffffffffu, mx, o));
    }
    if ((t & 31) == 0) {
        atomicMin(&g_bmm[0], mn);
        atomicMax(&g_bmm[1], mx);
    }
}

// x fp32 -> fp16 + per-row sum
__global__ void k_xcvt(const float* __restrict__ x) {
    __shared__ float red[8];
    int row = blockIdx.x;
    int t = threadIdx.x;
    const float4* xr = (const float4*)(x + (size_t)row * IN_F);
    uint32_t o[4];
    float s = 0.f;
    #pragma unroll
    for (int j = 0; j < 4; j++) {
        float4 v = xr[t * 4 + j];
        s += v.x + v.y + v.z + v.w;
        __half2 p0 = __floats2half2_rn(v.x, v.y);
        __half2 p1 = __floats2half2_rn(v.z, v.w);
        o[2 * (j & 1)]     = *(uint32_t*)&p0;
        o[2 * (j & 1) + 1] = *(uint32_t*)&p1;
        if (j & 1) {
            size_t base = ((size_t)row * IN_F) / 8 + t * 2 + (j >> 1);
            ((uint4*)g_xh)[base] = make_uint4(o[0], o[1], o[2], o[3]);
        }
    }
    #pragma unroll
    for (int of = 16; of > 0; of >>= 1) s += __shfl_xor_sync(0xffffffffu, s, of);
    if ((t & 31) == 0) red[t >> 5] = s;
    __syncthreads();
    if (t == 0) {
        float tot = 0.f;
        #pragma unroll
        for (int i = 0; i < 8; i++) tot += red[i];
        g_rowsum[row] = tot;
    }
}

__global__ void k_scal(const float* wmin, const float* wmax, const float* bmin, const float* bmax) {
    float s_w = (*wmax - *wmin) / (float)(g_wmm[1] - g_wmm[0]);
    g_scal[0] = s_w;
    g_scal[1] = *wmin - s_w * (float)g_wmm[0];
    float s_b = (*bmax - *bmin) / (float)(g_bmm[1] - g_bmm[0]);
    g_scal[2] = s_b;
    g_scal[3] = *bmin - s_b * (float)g_bmm[0];
}

// ---------------- GEMM ----------------
// CTA tile: 128 (M) x 256 (N), BK=64 fp16 (128B rows), 16 warps (2x8 of 64x32),
// 3-stage cp.async pipeline, SW128 swizzle, mma.sync m16n8k16 fp16.
#define BM      128
#define BN      256
#define BK      64
#define NSTAGE  3
#define NSTEPS  (IN_F / BK)          // 64
#define A_BYTES (BM * 128)           // 16384
#define B_BYTES (BN * 128)           // 32768
#define STG_B   (A_BYTES + B_BYTES)  // 49152
#define OFF_B   A_BYTES
#define SM_TOTAL (NSTAGE * STG_B)    // 147456
#define NTHR    512

__device__ __forceinline__ void issue_stage(char* smem, int stage, int tid,
                                            const __half* asrc,
                                            const __half* bsrc, int k0) {
    uint32_t ubase = smem_u32(smem + stage * STG_B);
    // A: 128 rows x 8 chunks of 16B; 4 threads per row, 2 chunks each
    {
        int r = tid >> 2;
        int c0 = (tid & 3) * 2;
        const char* src = (const char*)(asrc + (size_t)r * IN_F + k0);
        uint32_t rb = ubase + r * 128;
        int rx = r & 7;
        #pragma unroll
        for (int c = 0; c < 2; c++)
            CP_ASYNC16(rb + (((c0 + c) ^ rx) * 16), src + (c0 + c) * 16);
    }
    // B: 256 rows x 8 chunks; 2 threads per row, 4 chunks each
    {
        int r = tid >> 1;
        int c0 = (tid & 1) * 4;
        const char* src = (const char*)(bsrc + (size_t)r * IN_F + k0);
        uint32_t rb = ubase + OFF_B + r * 128;
        int rx = r & 7;
        #pragma unroll
        for (int c = 0; c < 4; c++)
            CP_ASYNC16(rb + (((c0 + c) ^ rx) * 16), src + (c0 + c) * 16);
    }
}

__global__ void __launch_bounds__(NTHR, 1) k_gemm(const int* __restrict__ bias_q,
                                                  float* __restrict__ out) {
    extern __shared__ char smem[];
    int tid = threadIdx.x;
    int wid = tid >> 5, lid = tid & 31;
    int n0 = blockIdx.x * BN;
    int m0 = blockIdx.y * BM;
    int wm = (wid >> 3) * 64;        // warp m offset (2 slots of 64)
    int wn = (wid & 7) * 32;         // warp n offset (8 slots of 32)

    const __half* asrc = g_xh + (size_t)m0 * IN_F;
    const __half* bsrc = g_wh + (size_t)n0 * IN_F;

    float acc[4][4][4];
    #pragma unroll
    for (int i = 0; i < 4; i++)
        #pragma unroll
        for (int j = 0; j < 4; j++)
            #pragma unroll
            for (int q = 0; q < 4; q++) acc[i][j][q] = 0.f;

    int lrow = lid & 15;
    int lkc  = (lid >> 4) & 1;       // extra 16B k-chunk for lanes 16-31
    int lx   = lrow & 7;             // swizzle xor
    uint32_t sbase = smem_u32(smem);

    uint32_t aRowOff[4], bRowOff[2];
    #pragma unroll
    for (int f = 0; f < 4; f++)
        aRowOff[f] = (wm + f * 16 + lrow) * 128;
    #pragma unroll
    for (int f = 0; f < 2; f++)
        bRowOff[f] = OFF_B + (wn + f * 16 + lrow) * 128;

    issue_stage(smem, 0, tid, asrc, bsrc, 0);
    CP_COMMIT();
    issue_stage(smem, 1, tid, asrc, bsrc, BK);
    CP_COMMIT();

    for (int s = 0; s < NSTEPS; s++) {
        CP_WAIT(1);
        __syncthreads();
        if (s + 2 < NSTEPS)
            issue_stage(smem, (s + 2) % NSTAGE, tid, asrc, bsrc, (s + 2) * BK);
        CP_COMMIT();   // unconditional: keeps group arithmetic valid at the tail
        uint32_t stg = sbase + (s % NSTAGE) * STG_B;
        #pragma unroll
        for (int k16 = 0; k16 < 4; k16++) {
            int kc = k16 * 2 + lkc;          // 16B chunk index within 128B row
            uint32_t b[4][2];
            #pragma unroll
            for (int f = 0; f < 2; f++) {
                uint32_t q0, q1, q2, q3;
                ldsm_x4(q0, q1, q2, q3, stg + bRowOff[f] + ((kc ^ lx) * 16));
                b[2 * f][0] = q0; b[2 * f + 1][0] = q1;
                b[2 * f][1] = q2; b[2 * f + 1][1] = q3;
            }
            uint32_t a[4][4];
            #pragma unroll
            for (int f = 0; f < 4; f++)
                ldsm_x4(a[f][0], a[f][1], a[f][2], a[f][3],
                        stg + aRowOff[f] + ((kc ^ lx) * 16));
            #pragma unroll
            for (int mf = 0; mf < 4; mf++)
                #pragma unroll
                for (int nf = 0; nf < 4; nf++)
                    mma16816(acc[mf][nf][0], acc[mf][nf][1], acc[mf][nf][2], acc[mf][nf][3],
                             a[mf][0], a[mf][1], a[mf][2], a[mf][3],
                             b[nf][0], b[nf][1]);
        }
        __syncthreads();
    }

    // ---------------- epilogue: y = s_w*D + off_w*rowsum + bias_deq ----------------
    float s_w = g_scal[0], off_w = g_scal[1];
    float s_b = g_scal[2], off_b = g_scal[3];
    float rs0[4], rs1[4];
    #pragma unroll
    for (int mf = 0; mf < 4; mf++) {
        int r = m0 + wm + mf * 16 + (lid >> 2);
        rs0[mf] = off_w * g_rowsum[r];
        rs1[mf] = off_w * g_rowsum[r + 8];
    }
    float bv[4][2];
    #pragma unroll
    for (int nf = 0; nf < 4; nf++) {
        int c = n0 + wn + nf * 8 + (lid & 3) * 2;
        bv[nf][0] = fmaf(s_b, (float)bias_q[c], off_b);
        bv[nf][1] = fmaf(s_b, (float)bias_q[c + 1], off_b);
    }
    #pragma unroll
    for (int mf = 0; mf < 4; mf++) {
        int r0 = m0 + wm + mf * 16 + (lid >> 2);
        #pragma unroll
        for (int nf = 0; nf < 4; nf++) {
            int c = n0 + wn + nf * 8 + (lid & 3) * 2;
            float2 v0, v1;
            v0.x = fmaf(s_w, acc[mf][nf][0], rs0[mf] + bv[nf][0]);
            v0.y = fmaf(s_w, acc[mf][nf][1], rs0[mf] + bv[nf][1]);
            v1.x = fmaf(s_w, acc[mf][nf][2], rs1[mf] + bv[nf][0]);
            v1.y = fmaf(s_w, acc[mf][nf][3], rs1[mf] + bv[nf][1]);
            *(float2*)(out + (size_t)r0 * OUT_F + c)       = v0;
            *(float2*)(out + (size_t)(r0 + 8) * OUT_F + c) = v1;
        }
    }
}

// ---------------- launch ----------------
extern "C" void kernel_launch(void* const* d_in, const int* in_sizes, int n_in,
                              void* d_out, int out_size) {
    const float* x    = (const float*)d_in[0];
    const int*   wq   = (const int*)d_in[1];
    const int*   bq   = (const int*)d_in[2];
    const float* wmin = (const float*)d_in[3];
    const float* wmax = (const float*)d_in[4];
    const float* bmin = (const float*)d_in[5];
    const float* bmax = (const float*)d_in[6];
    float* out = (float*)d_out;

    k_init<<<1, 1>>>();
    k_wconv<<<((size_t)OUT_F * IN_F / 4) / 256, 256>>>(wq);
    k_bias_mm<<<1, 256>>>(bq);
    k_xcvt<<<BATCH, 256>>>(x);
    k_scal<<<1, 1>>>(wmin, wmax, bmin, bmax);

    cudaFuncSetAttribute(k_gemm, cudaFuncAttributeMaxDynamicSharedMemorySize, SM_TOTAL);
    k_gemm<<<dim3(OUT_F / BN, BATCH / BM), NTHR, SM_TOTAL>>>(bq, out);
}

// round 6
// speedup vs baseline: 3.2613x; 1.0517x over previous
#include <cuda_runtime.h>
#include <cuda_fp16.h>
#include <stdint.h>

#define IN_F  4096
#define OUT_F 4096
#define BATCH 4096

// ---------------- scratch (static device globals; no allocation) ----------------
__device__ __align__(16) __half g_wh[(size_t)OUT_F * IN_F];   // 32 MB
__device__ __align__(16) __half g_xh[(size_t)BATCH * IN_F];   // 32 MB
__device__ float g_rowsum[BATCH];
__device__ int   g_wmm[2];    // weight q min, max
__device__ int   g_bmm[2];    // bias   q min, max
__device__ float g_scal[4];   // s_w, off_w, s_b, off_b

// ---------------- PTX helpers (legal at compute_103) ----------------
__device__ __forceinline__ uint32_t smem_u32(const void* p) {
    uint32_t a;
    asm("{ .reg .u64 t; cvta.to.shared.u64 t, %1; cvt.u32.u64 %0, t; }" : "=r"(a) : "l"(p));
    return a;
}

#define CP_ASYNC16(dst, src) \
    asm volatile("cp.async.cg.shared.global [%0], [%1], 16;" :: "r"(dst), "l"(src))
#define CP_COMMIT() asm volatile("cp.async.commit_group;" ::: "memory")
#define CP_WAIT(n)  asm volatile("cp.async.wait_group %0;" :: "n"(n) : "memory")

__device__ __forceinline__ void ldsm_x4(uint32_t& d0, uint32_t& d1, uint32_t& d2, uint32_t& d3,
                                        uint32_t addr) {
    asm volatile("ldmatrix.sync.aligned.m8n8.x4.shared.b16 {%0,%1,%2,%3}, [%4];"
                 : "=r"(d0), "=r"(d1), "=r"(d2), "=r"(d3) : "r"(addr));
}

__device__ __forceinline__ void mma16816(float& c0, float& c1, float& c2, float& c3,
                                         uint32_t a0, uint32_t a1, uint32_t a2, uint32_t a3,
                                         uint32_t b0, uint32_t b1) {
    asm volatile(
        "mma.sync.aligned.m16n8k16.row.col.f32.f16.f16.f32 "
        "{%0,%1,%2,%3}, {%4,%5,%6,%7}, {%8,%9}, {%0,%1,%2,%3};"
        : "+f"(c0), "+f"(c1), "+f"(c2), "+f"(c3)
        : "r"(a0), "r"(a1), "r"(a2), "r"(a3), "r"(b0), "r"(b1));
}

// ---------------- prepass kernels ----------------
__global__ void k_init() {
    g_wmm[0] = 0x7fffffff; g_wmm[1] = (int)0x80000000;
    g_bmm[0] = 0x7fffffff; g_bmm[1] = (int)0x80000000;
}

// int32 weights -> fp16 (exact: |q| <= 128) + global min/max
__global__ void k_wconv(const int* __restrict__ wq) {
    int i = blockIdx.x * blockDim.x + threadIdx.x;     // one int4 per thread
    int4 v = ((const int4*)wq)[i];
    __half2 p0 = __floats2half2_rn((float)v.x, (float)v.y);
    __half2 p1 = __floats2half2_rn((float)v.z, (float)v.w);
    uint2 o;
    o.x = *(uint32_t*)&p0;
    o.y = *(uint32_t*)&p1;
    ((uint2*)g_wh)[i] = o;
    int mn = min(min(v.x, v.y), min(v.z, v.w));
    int mx = max(max(v.x, v.y), max(v.z, v.w));
    #pragma unroll
    for (int o2 = 16; o2 > 0; o2 >>= 1) {
        mn = min(mn, __shfl_xor_sync(0xffffffffu, mn, o2));
        mx = max(mx, __shfl_xor_sync(0xffffffffu, mx, o2));
    }
    if ((threadIdx.x & 31) == 0) {
        atomicMin(&g_wmm[0], mn);
        atomicMax(&g_wmm[1], mx);
    }
}

__global__ void k_bias_mm(const int* __restrict__ bq) {
    int t = threadIdx.x;
    int mn = 0x7fffffff, mx = (int)0x80000000;
    for (int i = t; i < OUT_F; i += 256) {
        int v = bq[i];
        mn = min(mn, v); mx = max(mx, v);
    }
    #pragma unroll
    for (int o = 16; o > 0; o >>= 1) {
        mn = min(mn, __shfl_xor_sync(0xffffffffu, mn, o));
        mx = max(mx, __shfl_xor_sync(0xffffffffu, mx, o));
    }
    if ((t & 31) == 0) {
        atomicMin(&g_bmm[0], mn);
        atomicMax(&g_bmm[1], mx);
    }
}

// x fp32 -> fp16 + per-row sum
__global__ void k_xcvt(const float* __restrict__ x) {
    __shared__ float red[8];
    int row = blockIdx.x;
    int t = threadIdx.x;
    const float4* xr = (const float4*)(x + (size_t)row * IN_F);
    uint32_t o[4];
    float s = 0.f;
    #pragma unroll
    for (int j = 0; j < 4; j++) {
        float4 v = xr[t * 4 + j];
        s += v.x + v.y + v.z + v.w;
        __half2 p0 = __floats2half2_rn(v.x, v.y);
        __half2 p1 = __floats2half2_rn(v.z, v.w);
        o[2 * (j & 1)]     = *(uint32_t*)&p0;
        o[2 * (j & 1) + 1] = *(uint32_t*)&p1;
        if (j & 1) {
            size_t base = ((size_t)row * IN_F) / 8 + t * 2 + (j >> 1);
            ((uint4*)g_xh)[base] = make_uint4(o[0], o[1], o[2], o[3]);
        }
    }
    #pragma unroll
    for (int of = 16; of > 0; of >>= 1) s += __shfl_xor_sync(0xffffffffu, s, of);
    if ((t & 31) == 0) red[t >> 5] = s;
    __syncthreads();
    if (t == 0) {
        float tot = 0.f;
        #pragma unroll
        for (int i = 0; i < 8; i++) tot += red[i];
        g_rowsum[row] = tot;
    }
}

__global__ void k_scal(const float* wmin, const float* wmax, const float* bmin, const float* bmax) {
    float s_w = (*wmax - *wmin) / (float)(g_wmm[1] - g_wmm[0]);
    g_scal[0] = s_w;
    g_scal[1] = *wmin - s_w * (float)g_wmm[0];
    float s_b = (*bmax - *bmin) / (float)(g_bmm[1] - g_bmm[0]);
    g_scal[2] = s_b;
    g_scal[3] = *bmin - s_b * (float)g_bmm[0];
}

// ---------------- GEMM ----------------
// CTA tile: 128 (M) x 128 (N), BK=64 fp16 (128B rows), 8 warps (2x4 of 64x32),
// 3-stage cp.async pipeline, SW128 swizzle, 2 CTAs/SM.
#define BM      128
#define BN      128
#define BK      64
#define NSTAGE  3
#define NSTEPS  (IN_F / BK)          // 64
#define A_BYTES (BM * 128)           // 16384
#define B_BYTES (BN * 128)           // 16384
#define STG_B   (A_BYTES + B_BYTES)  // 32768
#define OFF_B   A_BYTES
#define SM_TOTAL (NSTAGE * STG_B)    // 98304
#define NTHR    256

__device__ __forceinline__ void issue_stage(char* smem, int stage, int tid,
                                            const __half* asrc,
                                            const __half* bsrc, int k0) {
    uint32_t ubase = smem_u32(smem + stage * STG_B);
    // A: 128 rows x 8 chunks of 16B; 2 threads per row, 4 chunks each
    {
        int r = tid >> 1;
        int c0 = (tid & 1) * 4;
        const char* src = (const char*)(asrc + (size_t)r * IN_F + k0);
        uint32_t rb = ubase + r * 128;
        int rx = r & 7;
        #pragma unroll
        for (int c = 0; c < 4; c++)
            CP_ASYNC16(rb + (((c0 + c) ^ rx) * 16), src + (c0 + c) * 16);
    }
    // B: 128 rows x 8 chunks; 2 threads per row, 4 chunks each
    {
        int r = tid >> 1;
        int c0 = (tid & 1) * 4;
        const char* src = (const char*)(bsrc + (size_t)r * IN_F + k0);
        uint32_t rb = ubase + OFF_B + r * 128;
        int rx = r & 7;
        #pragma unroll
        for (int c = 0; c < 4; c++)
            CP_ASYNC16(rb + (((c0 + c) ^ rx) * 16), src + (c0 + c) * 16);
    }
}

__global__ void __launch_bounds__(NTHR, 2) k_gemm(const int* __restrict__ bias_q,
                                                  float* __restrict__ out) {
    extern __shared__ char smem[];
    int tid = threadIdx.x;
    int wid = tid >> 5, lid = tid & 31;
    int n0 = blockIdx.x * BN;
    int m0 = blockIdx.y * BM;
    int wm = (wid >> 2) * 64;        // warp m offset (2 slots of 64)
    int wn = (wid & 3) * 32;         // warp n offset (4 slots of 32)

    const __half* asrc = g_xh + (size_t)m0 * IN_F;
    const __half* bsrc = g_wh + (size_t)n0 * IN_F;

    float acc[4][4][4];
    #pragma unroll
    for (int i = 0; i < 4; i++)
        #pragma unroll
        for (int j = 0; j < 4; j++)
            #pragma unroll
            for (int q = 0; q < 4; q++) acc[i][j][q] = 0.f;

    int lrow = lid & 15;
    int lkc  = (lid >> 4) & 1;       // extra 16B k-chunk for lanes 16-31
    int lx   = lrow & 7;             // swizzle xor
    uint32_t sbase = smem_u32(smem);

    uint32_t aRowOff[4], bRowOff[2];
    #pragma unroll
    for (int f = 0; f < 4; f++)
        aRowOff[f] = (wm + f * 16 + lrow) * 128;
    #pragma unroll
    for (int f = 0; f < 2; f++)
        bRowOff[f] = OFF_B + (wn + f * 16 + lrow) * 128;

    issue_stage(smem, 0, tid, asrc, bsrc, 0);
    CP_COMMIT();
    issue_stage(smem, 1, tid, asrc, bsrc, BK);
    CP_COMMIT();

    for (int s = 0; s < NSTEPS; s++) {
        CP_WAIT(1);
        __syncthreads();
        if (s + 2 < NSTEPS)
            issue_stage(smem, (s + 2) % NSTAGE, tid, asrc, bsrc, (s + 2) * BK);
        CP_COMMIT();   // unconditional: keeps group arithmetic valid at the tail
        uint32_t stg = sbase + (s % NSTAGE) * STG_B;
        #pragma unroll
        for (int k16 = 0; k16 < 4; k16++) {
            int kc = k16 * 2 + lkc;          // 16B chunk index within 128B row
            uint32_t b[4][2];
            #pragma unroll
            for (int f = 0; f < 2; f++) {
                uint32_t q0, q1, q2, q3;
                ldsm_x4(q0, q1, q2, q3, stg + bRowOff[f] + ((kc ^ lx) * 16));
                b[2 * f][0] = q0; b[2 * f + 1][0] = q1;
                b[2 * f][1] = q2; b[2 * f + 1][1] = q3;
            }
            uint32_t a[4][4];
            #pragma unroll
            for (int f = 0; f < 4; f++)
                ldsm_x4(a[f][0], a[f][1], a[f][2], a[f][3],
                        stg + aRowOff[f] + ((kc ^ lx) * 16));
            #pragma unroll
            for (int mf = 0; mf < 4; mf++)
                #pragma unroll
                for (int nf = 0; nf < 4; nf++)
                    mma16816(acc[mf][nf][0], acc[mf][nf][1], acc[mf][nf][2], acc[mf][nf][3],
                             a[mf][0], a[mf][1], a[mf][2], a[mf][3],
                             b[nf][0], b[nf][1]);
        }
        __syncthreads();
    }

    // ---------------- epilogue: y = s_w*D + off_w*rowsum + bias_deq ----------------
    float s_w = g_scal[0], off_w = g_scal[1];
    float s_b = g_scal[2], off_b = g_scal[3];
    float rs0[4], rs1[4];
    #pragma unroll
    for (int mf = 0; mf < 4; mf++) {
        int r = m0 + wm + mf * 16 + (lid >> 2);
        rs0[mf] = off_w * g_rowsum[r];
        rs1[mf] = off_w * g_rowsum[r + 8];
    }
    float bv[4][2];
    #pragma unroll
    for (int nf = 0; nf < 4; nf++) {
        int c = n0 + wn + nf * 8 + (lid & 3) * 2;
        bv[nf][0] = fmaf(s_b, (float)bias_q[c], off_b);
        bv[nf][1] = fmaf(s_b, (float)bias_q[c + 1], off_b);
    }
    #pragma unroll
    for (int mf = 0; mf < 4; mf++) {
        int r0 = m0 + wm + mf * 16 + (lid >> 2);
        #pragma unroll
        for (int nf = 0; nf < 4; nf++) {
            int c = n0 + wn + nf * 8 + (lid & 3) * 2;
            float2 v0, v1;
            v0.x = fmaf(s_w, acc[mf][nf][0], rs0[mf] + bv[nf][0]);
            v0.y = fmaf(s_w, acc[mf][nf][1], rs0[mf] + bv[nf][1]);
            v1.x = fmaf(s_w, acc[mf][nf][2], rs1[mf] + bv[nf][0]);
            v1.y = fmaf(s_w, acc[mf][nf][3], rs1[mf] + bv[nf][1]);
            *(float2*)(out + (size_t)r0 * OUT_F + c)       = v0;
            *(float2*)(out + (size_t)(r0 + 8) * OUT_F + c) = v1;
        }
    }
}

// ---------------- launch ----------------
extern "C" void kernel_launch(void* const* d_in, const int* in_sizes, int n_in,
                              void* d_out, int out_size) {
    const float* x    = (const float*)d_in[0];
    const int*   wq   = (const int*)d_in[1];
    const int*   bq   = (const int*)d_in[2];
    const float* wmin = (const float*)d_in[3];
    const float* wmax = (const float*)d_in[4];
    const float* bmin = (const float*)d_in[5];
    const float* bmax = (const float*)d_in[6];
    float* out = (float*)d_out;

    k_init<<<1, 1>>>();
    k_wconv<<<((size_t)OUT_F * IN_F / 4) / 256, 256>>>(wq);
    k_bias_mm<<<1, 256>>>(bq);
    k_xcvt<<<BATCH, 256>>>(x);
    k_scal<<<1, 1>>>(wmin, wmax, bmin, bmax);

    cudaFuncSetAttribute(k_gemm, cudaFuncAttributeMaxDynamicSharedMemorySize, SM_TOTAL);
    k_gemm<<<dim3(OUT_F / BN, BATCH / BM), NTHR, SM_TOTAL>>>(bq, out);
}